// round 1
// baseline (speedup 1.0000x reference)
#include <cuda_runtime.h>
#include <math.h>

#define FDIM 256
#define TOUT 8
#define N_MONO 150000
#define N_CLEAV 100000
#define N_FRAG 80000
#define N_OUTN 40000

// ---- scratch (device globals: allocation-free rule) ----
__device__ float g_cleav[(size_t)N_CLEAV * 2 * FDIM];        // [100000, 512]
__device__ float g_gates[(size_t)N_FRAG * 2 * 4 * FDIM];     // [160000, 1024]
__device__ float g_h1[(size_t)N_FRAG * FDIM];
__device__ float g_c1[(size_t)N_FRAG * FDIM];
__device__ float g_fragout[(size_t)N_FRAG * TOUT];

__device__ __forceinline__ float warp_sum(float v) {
#pragma unroll
    for (int o = 16; o; o >>= 1) v += __shfl_xor_sync(0xffffffffu, v, o);
    return v;
}

__device__ __forceinline__ float sigf(float x) { return 1.0f / (1.0f + expf(-x)); }

// ============================================================
// K1: cleavage attention pull (lost + retained), one block per cleavage node
// ============================================================
__global__ __launch_bounds__(256) void cleav_kernel(
    const float* __restrict__ feature,
    const float* __restrict__ WgL,
    const float* __restrict__ WgR,
    const int* __restrict__ lost_src,
    const int* __restrict__ ret_src)
{
    __shared__ float sh[8][FDIM];
    __shared__ float logit[8];
    int i = blockIdx.x;
    int tid = threadIdx.x;

#pragma unroll
    for (int d = 0; d < 4; d++) {
        sh[d][tid]     = feature[(size_t)lost_src[i * 4 + d] * FDIM + tid];
        sh[4 + d][tid] = feature[(size_t)ret_src[i * 4 + d]  * FDIM + tid];
    }
    __syncthreads();

    int w = tid >> 5, lane = tid & 31;
    const float* Wg = (w < 4) ? WgL : WgR;
    float p = 0.f;
#pragma unroll
    for (int s = 0; s < FDIM; s += 32) p += sh[w][lane + s] * Wg[lane + s];
    p = warp_sum(p);
    if (lane == 0) logit[w] = p;
    __syncthreads();

    // lost softmax over 4 neighbors
    {
        float m = fmaxf(fmaxf(logit[0], logit[1]), fmaxf(logit[2], logit[3]));
        float e0 = expf(logit[0] - m), e1 = expf(logit[1] - m);
        float e2 = expf(logit[2] - m), e3 = expf(logit[3] - m);
        float inv = 1.0f / (e0 + e1 + e2 + e3);
        float o = (e0 * sh[0][tid] + e1 * sh[1][tid] + e2 * sh[2][tid] + e3 * sh[3][tid]) * inv;
        g_cleav[(size_t)i * 2 * FDIM + tid] = o;
    }
    // retained
    {
        float m = fmaxf(fmaxf(logit[4], logit[5]), fmaxf(logit[6], logit[7]));
        float e0 = expf(logit[4] - m), e1 = expf(logit[5] - m);
        float e2 = expf(logit[6] - m), e3 = expf(logit[7] - m);
        float inv = 1.0f / (e0 + e1 + e2 + e3);
        float o = (e0 * sh[4][tid] + e1 * sh[5][tid] + e2 * sh[6][tid] + e3 * sh[7][tid]) * inv;
        g_cleav[(size_t)i * 2 * FDIM + FDIM + tid] = o;
    }
}

// ============================================================
// GEMM: C[r][n] = sum_k A[row(r)][k] * W[n][k]  (+bias / +=C)
// BM=BN=64, BK=16, 256 threads, 4x4 microtile.
// GATHER: A row index through rowidx. ACCUM: C += (no bias).
// ============================================================
template <bool GATHER, bool ACCUM>
__global__ __launch_bounds__(256) void gemm_nt(
    const float* __restrict__ A, const int* __restrict__ rowidx,
    const float* __restrict__ W,
    const float* __restrict__ bias1, const float* __restrict__ bias2,
    float* __restrict__ C, int K, int ldc)
{
    const int BM = 64, BN = 64, BK = 16;
    __shared__ float As[BK][BM];
    __shared__ float Ws[BK][BN];

    int tid = threadIdx.x;
    int bm = blockIdx.y * BM;
    int bn = blockIdx.x * BN;

    int lrow = tid >> 2;          // 0..63
    int lk = (tid & 3) << 2;      // 0,4,8,12

    const float* Ap;
    if (GATHER) Ap = A + (size_t)rowidx[bm + lrow] * K + lk;
    else        Ap = A + (size_t)(bm + lrow) * K + lk;
    const float* Wp = W + (size_t)(bn + lrow) * K + lk;

    int ty = tid >> 4;  // 0..15 -> rows ty*4..
    int tx = tid & 15;  // 0..15 -> cols tx*4..
    float acc[4][4] = {};

    for (int k0 = 0; k0 < K; k0 += BK) {
        float4 av = *(const float4*)(Ap + k0);
        float4 wv = *(const float4*)(Wp + k0);
        __syncthreads();
        As[lk + 0][lrow] = av.x; As[lk + 1][lrow] = av.y;
        As[lk + 2][lrow] = av.z; As[lk + 3][lrow] = av.w;
        Ws[lk + 0][lrow] = wv.x; Ws[lk + 1][lrow] = wv.y;
        Ws[lk + 2][lrow] = wv.z; Ws[lk + 3][lrow] = wv.w;
        __syncthreads();
#pragma unroll
        for (int kk = 0; kk < BK; kk++) {
            float4 a4 = *(const float4*)&As[kk][ty << 2];
            float4 w4 = *(const float4*)&Ws[kk][tx << 2];
            float ar[4] = {a4.x, a4.y, a4.z, a4.w};
            float wr[4] = {w4.x, w4.y, w4.z, w4.w};
#pragma unroll
            for (int i = 0; i < 4; i++)
#pragma unroll
                for (int j = 0; j < 4; j++) acc[i][j] = fmaf(ar[i], wr[j], acc[i][j]);
        }
    }

#pragma unroll
    for (int i = 0; i < 4; i++) {
        int r = bm + (ty << 2) + i;
        float* Cr = C + (size_t)r * ldc + bn + (tx << 2);
#pragma unroll
        for (int j = 0; j < 4; j++) {
            float v = acc[i][j];
            if (ACCUM) v += Cr[j];
            else       v += bias1[bn + (tx << 2) + j] + bias2[bn + (tx << 2) + j];
            Cr[j] = v;
        }
    }
}

// ============================================================
// K3: LSTM step 0 elementwise (h=c=0): c1 = sig(i)*tanh(g), h1 = sig(o)*tanh(c1)
// ============================================================
__global__ __launch_bounds__(256) void lstm_step0(void)
{
    int e = blockIdx.x * 256 + threadIdx.x;   // e < N_FRAG*256
    int f = e >> 8, j = e & 255;
    const float* gb = g_gates + (size_t)(2 * f) * 1024;
    float ig = gb[j], gg = gb[512 + j], og = gb[768 + j];
    float c1 = sigf(ig) * tanhf(gg);
    float h1 = sigf(og) * tanhf(c1);
    g_c1[e] = c1;
    g_h1[e] = h1;
}

// ============================================================
// K5: LSTM step 1 + attention over {h1,h2} + output head (relu(frag@W_out+b))
// one block (256 threads) per fragment
// ============================================================
__global__ __launch_bounds__(256) void lstm_step1_attn_out(
    const float* __restrict__ Wg_frag,
    const float* __restrict__ W_out,
    const float* __restrict__ b_out)
{
    int f = blockIdx.x;
    int j = threadIdx.x;
    const float* gb = g_gates + (size_t)(2 * f + 1) * 1024;
    float ig = gb[j], fg = gb[256 + j], gg = gb[512 + j], og = gb[768 + j];
    float c1 = g_c1[(size_t)f * 256 + j];
    float c2 = sigf(fg) * c1 + sigf(ig) * tanhf(gg);
    float h2 = sigf(og) * tanhf(c2);
    float h1 = g_h1[(size_t)f * 256 + j];

    float wg = Wg_frag[j];
    __shared__ float red[8][2];
    float p1 = warp_sum(h1 * wg);
    float p2 = warp_sum(h2 * wg);
    int w = j >> 5, lane = j & 31;
    if (lane == 0) { red[w][0] = p1; red[w][1] = p2; }
    __syncthreads();
    float l1 = 0.f, l2 = 0.f;
#pragma unroll
    for (int ww = 0; ww < 8; ww++) { l1 += red[ww][0]; l2 += red[ww][1]; }
    float m = fmaxf(l1, l2);
    float e1 = expf(l1 - m), e2 = expf(l2 - m);
    float inv = 1.0f / (e1 + e2);
    float frag = (e1 * h1 + e2 * h2) * inv;

    // output head: out[t] = sum_j frag_j * W_out[j][t]
    float4 w0 = *(const float4*)&W_out[(size_t)j * 8];
    float4 w1 = *(const float4*)&W_out[(size_t)j * 8 + 4];
    float o[8] = {frag * w0.x, frag * w0.y, frag * w0.z, frag * w0.w,
                  frag * w1.x, frag * w1.y, frag * w1.z, frag * w1.w};
#pragma unroll
    for (int t = 0; t < 8; t++) o[t] = warp_sum(o[t]);
    __shared__ float red2[8][8];
    if (lane == 0) {
#pragma unroll
        for (int t = 0; t < 8; t++) red2[w][t] = o[t];
    }
    __syncthreads();
    if (j < 8) {
        float s = 0.f;
#pragma unroll
        for (int ww = 0; ww < 8; ww++) s += red2[ww][j];
        s += b_out[j];
        g_fragout[(size_t)f * 8 + j] = fmaxf(s, 0.f);
    }
}

// ============================================================
// K6: combine scatter-sum: out[n][t] = sum_d fragout[combine_src[n][d]][t]
// ============================================================
__global__ __launch_bounds__(256) void combine_kernel(
    const int* __restrict__ src, float* __restrict__ out)
{
    int idx = blockIdx.x * 256 + threadIdx.x;
    if (idx >= N_OUTN * TOUT) return;
    int n = idx >> 3, t = idx & 7;
    float s = 0.f;
#pragma unroll
    for (int d = 0; d < 4; d++)
        s += g_fragout[(size_t)src[n * 4 + d] * 8 + t];
    out[idx] = s;
}

// ============================================================
extern "C" void kernel_launch(void* const* d_in, const int* in_sizes, int n_in,
                              void* d_out, int out_size)
{
    const float* feature = (const float*)d_in[0];
    const float* WgL     = (const float*)d_in[1];
    const float* WgR     = (const float*)d_in[2];
    const float* W_ih    = (const float*)d_in[3];
    const float* W_hh    = (const float*)d_in[4];
    const float* b_ih    = (const float*)d_in[5];
    const float* b_hh    = (const float*)d_in[6];
    const float* Wg_frag = (const float*)d_in[7];
    const float* W_out   = (const float*)d_in[8];
    const float* b_out   = (const float*)d_in[9];
    const int* lost      = (const int*)d_in[10];
    const int* ret       = (const int*)d_in[11];
    const int* join      = (const int*)d_in[12];
    const int* comb      = (const int*)d_in[13];
    float* out = (float*)d_out;

    void *p_cleav, *p_gates, *p_h1;
    cudaGetSymbolAddress(&p_cleav, g_cleav);
    cudaGetSymbolAddress(&p_gates, g_gates);
    cudaGetSymbolAddress(&p_h1, g_h1);

    // K1: cleavage attention
    cleav_kernel<<<N_CLEAV, 256>>>(feature, WgL, WgR, lost, ret);

    // GEMM1: gates[160000,1024] = cleav[join_src][.,512] @ W_ih^T + (b_ih+b_hh)
    gemm_nt<true, false><<<dim3(1024 / 64, (2 * N_FRAG) / 64), 256>>>(
        (const float*)p_cleav, join, W_ih, b_ih, b_hh,
        (float*)p_gates, 512, 1024);

    // K3: LSTM step 0 elementwise
    lstm_step0<<<(N_FRAG * FDIM) / 256, 256>>>();

    // GEMM2: gates[odd rows] += h1 @ W_hh^T   (C base offset 1024, ldc 2048)
    gemm_nt<false, true><<<dim3(1024 / 64, N_FRAG / 64), 256>>>(
        (const float*)p_h1, nullptr, W_hh, nullptr, nullptr,
        (float*)p_gates + 1024, 256, 2048);

    // K5: LSTM step 1 + attention + output head
    lstm_step1_attn_out<<<N_FRAG, 256>>>(Wg_frag, W_out, b_out);

    // K6: combine scatter-sum
    combine_kernel<<<(N_OUTN * TOUT + 255) / 256, 256>>>(comb, out);
}

// round 3
// speedup vs baseline: 3.1226x; 3.1226x over previous
#include <cuda_runtime.h>
#include <math.h>
#include <stdint.h>

#define FDIM 256
#define TOUT 8
#define N_MONO 150000
#define N_CLEAV 100000
#define N_FRAG 80000
#define N_OUTN 40000

// ---- scratch (device globals: allocation-free rule) ----
__device__ float g_cleav[(size_t)N_CLEAV * 2 * FDIM];        // [100000, 512]
__device__ float g_gates[(size_t)N_FRAG * 2 * 4 * FDIM];     // [160000, 1024]
__device__ float g_h1[(size_t)N_FRAG * FDIM];
__device__ float g_c1[(size_t)N_FRAG * FDIM];
__device__ float g_fragout[(size_t)N_FRAG * TOUT];

__device__ __forceinline__ float warp_sum(float v) {
#pragma unroll
    for (int o = 16; o; o >>= 1) v += __shfl_xor_sync(0xffffffffu, v, o);
    return v;
}
__device__ __forceinline__ float sigf(float x) { return 1.0f / (1.0f + expf(-x)); }

__device__ __forceinline__ uint32_t f2tf(float x) {
    uint32_t u;
    asm("cvt.rna.tf32.f32 %0, %1;" : "=r"(u) : "f"(x));
    return u;
}

__device__ __forceinline__ void mma_tf32(float* d, const uint32_t* a, const uint32_t* b) {
    asm volatile(
        "mma.sync.aligned.m16n8k8.row.col.f32.tf32.tf32.f32 "
        "{%0,%1,%2,%3}, {%4,%5,%6,%7}, {%8,%9}, {%0,%1,%2,%3};"
        : "+f"(d[0]), "+f"(d[1]), "+f"(d[2]), "+f"(d[3])
        : "r"(a[0]), "r"(a[1]), "r"(a[2]), "r"(a[3]), "r"(b[0]), "r"(b[1]));
}

// ============================================================
// K1: cleavage attention pull (lost + retained), one block per cleavage node
// ============================================================
__global__ __launch_bounds__(256) void cleav_kernel(
    const float* __restrict__ feature,
    const float* __restrict__ WgL,
    const float* __restrict__ WgR,
    const int* __restrict__ lost_src,
    const int* __restrict__ ret_src)
{
    __shared__ float sh[8][FDIM];
    __shared__ float logit[8];
    int i = blockIdx.x;
    int tid = threadIdx.x;

#pragma unroll
    for (int d = 0; d < 4; d++) {
        sh[d][tid]     = feature[(size_t)lost_src[i * 4 + d] * FDIM + tid];
        sh[4 + d][tid] = feature[(size_t)ret_src[i * 4 + d]  * FDIM + tid];
    }
    __syncthreads();

    int w = tid >> 5, lane = tid & 31;
    const float* Wg = (w < 4) ? WgL : WgR;
    float p = 0.f;
#pragma unroll
    for (int s = 0; s < FDIM; s += 32) p += sh[w][lane + s] * Wg[lane + s];
    p = warp_sum(p);
    if (lane == 0) logit[w] = p;
    __syncthreads();

    {
        float m = fmaxf(fmaxf(logit[0], logit[1]), fmaxf(logit[2], logit[3]));
        float e0 = expf(logit[0] - m), e1 = expf(logit[1] - m);
        float e2 = expf(logit[2] - m), e3 = expf(logit[3] - m);
        float inv = 1.0f / (e0 + e1 + e2 + e3);
        float o = (e0 * sh[0][tid] + e1 * sh[1][tid] + e2 * sh[2][tid] + e3 * sh[3][tid]) * inv;
        g_cleav[(size_t)i * 2 * FDIM + tid] = o;
    }
    {
        float m = fmaxf(fmaxf(logit[4], logit[5]), fmaxf(logit[6], logit[7]));
        float e0 = expf(logit[4] - m), e1 = expf(logit[5] - m);
        float e2 = expf(logit[6] - m), e3 = expf(logit[7] - m);
        float inv = 1.0f / (e0 + e1 + e2 + e3);
        float o = (e0 * sh[4][tid] + e1 * sh[5][tid] + e2 * sh[6][tid] + e3 * sh[7][tid]) * inv;
        g_cleav[(size_t)i * 2 * FDIM + FDIM + tid] = o;
    }
}

// ============================================================
// tf32 mma.sync GEMM: C[r][n] = sum_k A[row(r)][k] * W[n][k]  (+bias / +=C)
// BM=128, BN=128, BK=16. 256 threads = 8 warps (4 x 2), warp tile 32x64.
// Double-buffered smem, stride 20 (conflict-free for frag pattern).
// ============================================================
#define STR 20
template <bool GATHER, bool ACCUM>
__global__ __launch_bounds__(256, 2) void gemm_mma(
    const float* __restrict__ A, const int* __restrict__ rowidx,
    const float* __restrict__ W,
    const float* __restrict__ bias1, const float* __restrict__ bias2,
    float* __restrict__ C, int K, int ldc)
{
    const int BM = 128, BK = 16;
    __shared__ int sidx[BM];
    __shared__ uint32_t As[2][BM * STR];
    __shared__ uint32_t Bs[2][BM * STR];

    int tid = threadIdx.x;
    int bm = blockIdx.y * BM;
    int bn = blockIdx.x * BM;

    if (GATHER && tid < BM) sidx[tid] = rowidx[bm + tid];
    __syncthreads();

    int r0 = tid >> 2;          // 0..63
    int p = tid & 3;            // float4 slot within 16-wide k
    const float *arow0, *arow1;
    if (GATHER) {
        arow0 = A + (size_t)sidx[r0] * K;
        arow1 = A + (size_t)sidx[r0 + 64] * K;
    } else {
        arow0 = A + (size_t)(bm + r0) * K;
        arow1 = A + (size_t)(bm + r0 + 64) * K;
    }
    const float* brow0 = W + (size_t)(bn + r0) * K;
    const float* brow1 = W + (size_t)(bn + r0 + 64) * K;

    int w = tid >> 5, lane = tid & 31;
    int wm = w & 3;             // 0..3 row group (32 rows)
    int wn = w >> 2;            // 0..1 col group (64 cols)
    int g = lane >> 2, c = lane & 3;

    float acc[2][8][4];
#pragma unroll
    for (int mt = 0; mt < 2; mt++)
#pragma unroll
        for (int nt = 0; nt < 8; nt++)
#pragma unroll
            for (int q = 0; q < 4; q++) acc[mt][nt][q] = 0.f;

    float4 a0, a1, b0, b1;
    int NS = K / BK;

    // prologue: load + store tile 0
    {
        a0 = *(const float4*)(arow0 + p * 4);
        a1 = *(const float4*)(arow1 + p * 4);
        b0 = *(const float4*)(brow0 + p * 4);
        b1 = *(const float4*)(brow1 + p * 4);
        uint4 t;
        t.x = f2tf(a0.x); t.y = f2tf(a0.y); t.z = f2tf(a0.z); t.w = f2tf(a0.w);
        *(uint4*)&As[0][r0 * STR + p * 4] = t;
        t.x = f2tf(a1.x); t.y = f2tf(a1.y); t.z = f2tf(a1.z); t.w = f2tf(a1.w);
        *(uint4*)&As[0][(r0 + 64) * STR + p * 4] = t;
        t.x = f2tf(b0.x); t.y = f2tf(b0.y); t.z = f2tf(b0.z); t.w = f2tf(b0.w);
        *(uint4*)&Bs[0][r0 * STR + p * 4] = t;
        t.x = f2tf(b1.x); t.y = f2tf(b1.y); t.z = f2tf(b1.z); t.w = f2tf(b1.w);
        *(uint4*)&Bs[0][(r0 + 64) * STR + p * 4] = t;
    }
    __syncthreads();

    for (int s = 0; s < NS; s++) {
        if (s + 1 < NS) {
            int k0 = (s + 1) * BK;
            a0 = *(const float4*)(arow0 + k0 + p * 4);
            a1 = *(const float4*)(arow1 + k0 + p * 4);
            b0 = *(const float4*)(brow0 + k0 + p * 4);
            b1 = *(const float4*)(brow1 + k0 + p * 4);
        }
        // compute on buffer s&1
        {
            const uint32_t* Ab = As[s & 1];
            const uint32_t* Bb = Bs[s & 1];
#pragma unroll
            for (int kk = 0; kk < 2; kk++) {
                uint32_t af[2][4];
#pragma unroll
                for (int mt = 0; mt < 2; mt++) {
                    const uint32_t* pa = Ab + (wm * 32 + mt * 16 + g) * STR + kk * 8 + c;
                    af[mt][0] = pa[0];
                    af[mt][1] = pa[8 * STR];
                    af[mt][2] = pa[4];
                    af[mt][3] = pa[8 * STR + 4];
                }
                uint32_t bf[8][2];
#pragma unroll
                for (int nt = 0; nt < 8; nt++) {
                    const uint32_t* pb = Bb + (wn * 64 + nt * 8 + g) * STR + kk * 8 + c;
                    bf[nt][0] = pb[0];
                    bf[nt][1] = pb[4];
                }
#pragma unroll
                for (int mt = 0; mt < 2; mt++)
#pragma unroll
                    for (int nt = 0; nt < 8; nt++)
                        mma_tf32(acc[mt][nt], af[mt], bf[nt]);
            }
        }
        if (s + 1 < NS) {
            int buf = (s + 1) & 1;
            uint4 t;
            t.x = f2tf(a0.x); t.y = f2tf(a0.y); t.z = f2tf(a0.z); t.w = f2tf(a0.w);
            *(uint4*)&As[buf][r0 * STR + p * 4] = t;
            t.x = f2tf(a1.x); t.y = f2tf(a1.y); t.z = f2tf(a1.z); t.w = f2tf(a1.w);
            *(uint4*)&As[buf][(r0 + 64) * STR + p * 4] = t;
            t.x = f2tf(b0.x); t.y = f2tf(b0.y); t.z = f2tf(b0.z); t.w = f2tf(b0.w);
            *(uint4*)&Bs[buf][r0 * STR + p * 4] = t;
            t.x = f2tf(b1.x); t.y = f2tf(b1.y); t.z = f2tf(b1.z); t.w = f2tf(b1.w);
            *(uint4*)&Bs[buf][(r0 + 64) * STR + p * 4] = t;
            __syncthreads();
        }
    }

    // epilogue
#pragma unroll
    for (int mt = 0; mt < 2; mt++) {
        int row0 = bm + wm * 32 + mt * 16 + g;
        int row1 = row0 + 8;
#pragma unroll
        for (int nt = 0; nt < 8; nt++) {
            int col = bn + wn * 64 + nt * 8 + 2 * c;
            float* c0 = C + (size_t)row0 * ldc + col;
            float* c1 = C + (size_t)row1 * ldc + col;
            if (ACCUM) {
                float2 o0 = *(const float2*)c0;
                float2 o1 = *(const float2*)c1;
                float2 n0 = {acc[mt][nt][0] + o0.x, acc[mt][nt][1] + o0.y};
                float2 n1 = {acc[mt][nt][2] + o1.x, acc[mt][nt][3] + o1.y};
                *(float2*)c0 = n0;
                *(float2*)c1 = n1;
            } else {
                float bs0 = bias1[col] + bias2[col];
                float bs1 = bias1[col + 1] + bias2[col + 1];
                float2 n0 = {acc[mt][nt][0] + bs0, acc[mt][nt][1] + bs1};
                float2 n1 = {acc[mt][nt][2] + bs0, acc[mt][nt][3] + bs1};
                *(float2*)c0 = n0;
                *(float2*)c1 = n1;
            }
        }
    }
}

// ============================================================
// K3: LSTM step 0 elementwise (h=c=0): c1 = sig(i)*tanh(g), h1 = sig(o)*tanh(c1)
// ============================================================
__global__ __launch_bounds__(256) void lstm_step0(void)
{
    int e = blockIdx.x * 256 + threadIdx.x;
    int f = e >> 8, j = e & 255;
    const float* gb = g_gates + (size_t)(2 * f) * 1024;
    float ig = gb[j], gg = gb[512 + j], og = gb[768 + j];
    float c1 = sigf(ig) * tanhf(gg);
    float h1 = sigf(og) * tanhf(c1);
    g_c1[e] = c1;
    g_h1[e] = h1;
}

// ============================================================
// K5: LSTM step 1 + attention over {h1,h2} + output head
// ============================================================
__global__ __launch_bounds__(256) void lstm_step1_attn_out(
    const float* __restrict__ Wg_frag,
    const float* __restrict__ W_out,
    const float* __restrict__ b_out)
{
    int f = blockIdx.x;
    int j = threadIdx.x;
    const float* gb = g_gates + (size_t)(2 * f + 1) * 1024;
    float ig = gb[j], fg = gb[256 + j], gg = gb[512 + j], og = gb[768 + j];
    float c1 = g_c1[(size_t)f * 256 + j];
    float c2 = sigf(fg) * c1 + sigf(ig) * tanhf(gg);
    float h2 = sigf(og) * tanhf(c2);
    float h1 = g_h1[(size_t)f * 256 + j];

    float wg = Wg_frag[j];
    __shared__ float red[8][2];
    float p1 = warp_sum(h1 * wg);
    float p2 = warp_sum(h2 * wg);
    int w = j >> 5, lane = j & 31;
    if (lane == 0) { red[w][0] = p1; red[w][1] = p2; }
    __syncthreads();
    float l1 = 0.f, l2 = 0.f;
#pragma unroll
    for (int ww = 0; ww < 8; ww++) { l1 += red[ww][0]; l2 += red[ww][1]; }
    float m = fmaxf(l1, l2);
    float e1 = expf(l1 - m), e2 = expf(l2 - m);
    float inv = 1.0f / (e1 + e2);
    float frag = (e1 * h1 + e2 * h2) * inv;

    float4 w0 = *(const float4*)&W_out[(size_t)j * 8];
    float4 w1 = *(const float4*)&W_out[(size_t)j * 8 + 4];
    float o[8] = {frag * w0.x, frag * w0.y, frag * w0.z, frag * w0.w,
                  frag * w1.x, frag * w1.y, frag * w1.z, frag * w1.w};
#pragma unroll
    for (int t = 0; t < 8; t++) o[t] = warp_sum(o[t]);
    __shared__ float red2[8][8];
    if (lane == 0) {
#pragma unroll
        for (int t = 0; t < 8; t++) red2[w][t] = o[t];
    }
    __syncthreads();
    if (j < 8) {
        float s = 0.f;
#pragma unroll
        for (int ww = 0; ww < 8; ww++) s += red2[ww][j];
        s += b_out[j];
        g_fragout[(size_t)f * 8 + j] = fmaxf(s, 0.f);
    }
}

// ============================================================
// K6: combine scatter-sum
// ============================================================
__global__ __launch_bounds__(256) void combine_kernel(
    const int* __restrict__ src, float* __restrict__ out)
{
    int idx = blockIdx.x * 256 + threadIdx.x;
    if (idx >= N_OUTN * TOUT) return;
    int n = idx >> 3, t = idx & 7;
    float s = 0.f;
#pragma unroll
    for (int d = 0; d < 4; d++)
        s += g_fragout[(size_t)src[n * 4 + d] * 8 + t];
    out[idx] = s;
}

// ============================================================
extern "C" void kernel_launch(void* const* d_in, const int* in_sizes, int n_in,
                              void* d_out, int out_size)
{
    const float* feature = (const float*)d_in[0];
    const float* WgL     = (const float*)d_in[1];
    const float* WgR     = (const float*)d_in[2];
    const float* W_ih    = (const float*)d_in[3];
    const float* W_hh    = (const float*)d_in[4];
    const float* b_ih    = (const float*)d_in[5];
    const float* b_hh    = (const float*)d_in[6];
    const float* Wg_frag = (const float*)d_in[7];
    const float* W_out   = (const float*)d_in[8];
    const float* b_out   = (const float*)d_in[9];
    const int* lost      = (const int*)d_in[10];
    const int* ret       = (const int*)d_in[11];
    const int* join      = (const int*)d_in[12];
    const int* comb      = (const int*)d_in[13];
    float* out = (float*)d_out;

    void *p_cleav, *p_gates, *p_h1;
    cudaGetSymbolAddress(&p_cleav, g_cleav);
    cudaGetSymbolAddress(&p_gates, g_gates);
    cudaGetSymbolAddress(&p_h1, g_h1);

    // K1: cleavage attention
    cleav_kernel<<<N_CLEAV, 256>>>(feature, WgL, WgR, lost, ret);

    // GEMM1: gates[160000,1024] = cleav[join_src][.,512] @ W_ih^T + (b_ih+b_hh)
    gemm_mma<true, false><<<dim3(1024 / 128, (2 * N_FRAG) / 128), 256>>>(
        (const float*)p_cleav, join, W_ih, b_ih, b_hh,
        (float*)p_gates, 512, 1024);

    // K3: LSTM step 0 elementwise
    lstm_step0<<<(N_FRAG * FDIM) / 256, 256>>>();

    // GEMM2: gates[odd rows] += h1 @ W_hh^T   (C base offset 1024, ldc 2048)
    gemm_mma<false, true><<<dim3(1024 / 128, N_FRAG / 128), 256>>>(
        (const float*)p_h1, nullptr, W_hh, nullptr, nullptr,
        (float*)p_gates + 1024, 256, 2048);

    // K5: LSTM step 1 + attention + output head
    lstm_step1_attn_out<<<N_FRAG, 256>>>(Wg_frag, W_out, b_out);

    // K6: combine scatter-sum
    combine_kernel<<<(N_OUTN * TOUT + 255) / 256, 256>>>(comb, out);
}

// round 4
// speedup vs baseline: 4.4360x; 1.4206x over previous
#include <cuda_runtime.h>
#include <cuda_fp16.h>
#include <math.h>
#include <stdint.h>

#define FDIM 256
#define TOUT 8
#define N_MONO 150000
#define N_CLEAV 100000
#define N_FRAG 80000
#define N_OUTN 40000

// ---- scratch (device globals: allocation-free rule) ----
__device__ __half g_cleav_h[(size_t)N_CLEAV * 2 * FDIM];     // [100000, 512] half
__device__ float  g_gates[(size_t)N_FRAG * 2 * 4 * FDIM];    // [160000, 1024] fp32
__device__ float  g_h1[(size_t)N_FRAG * FDIM];               // fp32 master
__device__ __half g_h1h[(size_t)N_FRAG * FDIM];              // half copy for GEMM2
__device__ float  g_c1[(size_t)N_FRAG * FDIM];
__device__ float  g_fragout[(size_t)N_FRAG * TOUT];
__device__ __half g_Wih_h[1024 * 512];
__device__ __half g_Whh_h[1024 * 256];

__device__ __forceinline__ float warp_sum(float v) {
#pragma unroll
    for (int o = 16; o; o >>= 1) v += __shfl_xor_sync(0xffffffffu, v, o);
    return v;
}
__device__ __forceinline__ float sigf(float x) { return 1.0f / (1.0f + expf(-x)); }

__device__ __forceinline__ uint32_t smem_u32(const void* p) {
    uint32_t a;
    asm("{ .reg .u64 t; cvta.to.shared.u64 t, %1; cvt.u32.u64 %0, t; }" : "=r"(a) : "l"(p));
    return a;
}
__device__ __forceinline__ void ldmx4(uint32_t* r, uint32_t addr) {
    asm volatile("ldmatrix.sync.aligned.m8n8.x4.shared.b16 {%0,%1,%2,%3}, [%4];"
        : "=r"(r[0]), "=r"(r[1]), "=r"(r[2]), "=r"(r[3]) : "r"(addr));
}
__device__ __forceinline__ void mma_f16(float* d, const uint32_t* a, const uint32_t* b) {
    asm volatile(
        "mma.sync.aligned.m16n8k16.row.col.f32.f16.f16.f32 "
        "{%0,%1,%2,%3}, {%4,%5,%6,%7}, {%8,%9}, {%0,%1,%2,%3};"
        : "+f"(d[0]), "+f"(d[1]), "+f"(d[2]), "+f"(d[3])
        : "r"(a[0]), "r"(a[1]), "r"(a[2]), "r"(a[3]), "r"(b[0]), "r"(b[1]));
}

// ============================================================
// K0: convert weights fp32 -> half (one-time per launch, tiny)
// ============================================================
__global__ __launch_bounds__(256) void conv_w(
    const float* __restrict__ Wih, const float* __restrict__ Whh)
{
    int i = blockIdx.x * 256 + threadIdx.x;
    if (i < 1024 * 512) g_Wih_h[i] = __float2half_rn(Wih[i]);
    if (i < 1024 * 256) g_Whh_h[i] = __float2half_rn(Whh[i]);
}

// ============================================================
// K1: cleavage attention pull, writes half output for GEMM1
// ============================================================
__global__ __launch_bounds__(256) void cleav_kernel(
    const float* __restrict__ feature,
    const float* __restrict__ WgL,
    const float* __restrict__ WgR,
    const int* __restrict__ lost_src,
    const int* __restrict__ ret_src)
{
    __shared__ float sh[8][FDIM];
    __shared__ float logit[8];
    int i = blockIdx.x;
    int tid = threadIdx.x;

#pragma unroll
    for (int d = 0; d < 4; d++) {
        sh[d][tid]     = feature[(size_t)lost_src[i * 4 + d] * FDIM + tid];
        sh[4 + d][tid] = feature[(size_t)ret_src[i * 4 + d]  * FDIM + tid];
    }
    __syncthreads();

    int w = tid >> 5, lane = tid & 31;
    const float* Wg = (w < 4) ? WgL : WgR;
    float p = 0.f;
#pragma unroll
    for (int s = 0; s < FDIM; s += 32) p += sh[w][lane + s] * Wg[lane + s];
    p = warp_sum(p);
    if (lane == 0) logit[w] = p;
    __syncthreads();

    {
        float m = fmaxf(fmaxf(logit[0], logit[1]), fmaxf(logit[2], logit[3]));
        float e0 = expf(logit[0] - m), e1 = expf(logit[1] - m);
        float e2 = expf(logit[2] - m), e3 = expf(logit[3] - m);
        float inv = 1.0f / (e0 + e1 + e2 + e3);
        float o = (e0 * sh[0][tid] + e1 * sh[1][tid] + e2 * sh[2][tid] + e3 * sh[3][tid]) * inv;
        g_cleav_h[(size_t)i * 2 * FDIM + tid] = __float2half_rn(o);
    }
    {
        float m = fmaxf(fmaxf(logit[4], logit[5]), fmaxf(logit[6], logit[7]));
        float e0 = expf(logit[4] - m), e1 = expf(logit[5] - m);
        float e2 = expf(logit[6] - m), e3 = expf(logit[7] - m);
        float inv = 1.0f / (e0 + e1 + e2 + e3);
        float o = (e0 * sh[4][tid] + e1 * sh[5][tid] + e2 * sh[6][tid] + e3 * sh[7][tid]) * inv;
        g_cleav_h[(size_t)i * 2 * FDIM + FDIM + tid] = __float2half_rn(o);
    }
}

// ============================================================
// fp16 mma.sync GEMM: C[r][n] = sum_k A[row(r)][k] * W[n][k]  (+bias / +=C)
// BM=BN=128, BK=32. 256 threads = 8 warps (4x2), warp tile 32x64.
// Double-buffered smem, 64B rows, XOR-swizzled 16B chunks, ldmatrix loads.
// ============================================================
template <bool GATHER, bool ACCUM>
__global__ __launch_bounds__(256, 2) void gemm_h(
    const __half* __restrict__ A, const int* __restrict__ rowidx,
    const __half* __restrict__ W,
    const float* __restrict__ bias1, const float* __restrict__ bias2,
    float* __restrict__ C, int K, int ldc)
{
    // each buffer: 128 rows x 32 halfs = 8192 bytes
    __shared__ __align__(16) __half As[2][128 * 32];
    __shared__ __align__(16) __half Bs[2][128 * 32];
    __shared__ int sidx[128];

    int tid = threadIdx.x;
    int bm = blockIdx.y * 128;
    int bn = blockIdx.x * 128;

    if (GATHER && tid < 128) sidx[tid] = rowidx[bm + tid];
    __syncthreads();

    // ---- global load mapping: thread -> (row, 16-half chunk pair) ----
    int lr = tid >> 1;          // 0..127
    int lh = tid & 1;           // which 16-half half-row
    const __half* arow = GATHER ? (A + (size_t)sidx[lr] * K)
                                : (A + (size_t)(bm + lr) * K);
    const __half* brow = W + (size_t)(bn + lr) * K;

    // smem store byte offsets (XOR swizzle: chunk q = j ^ ((row>>1)&3))
    int sw = (lr >> 1) & 3;
    uint32_t stA0 = lr * 64 + (((2 * lh)     ^ sw) << 4);
    uint32_t stA1 = lr * 64 + (((2 * lh + 1) ^ sw) << 4);

    uint32_t a_sb = smem_u32(As);
    uint32_t b_sb = smem_u32(Bs);

    // ---- ldmatrix address precompute (kk=0; kk=1 toggles bit5) ----
    int w = tid >> 5, lane = tid & 31;
    int wm = w & 3;             // row group (32 rows)
    int wn = w >> 2;            // col group (64 cols)
    uint32_t a_addr[2], b_addr[4];
#pragma unroll
    for (int mt = 0; mt < 2; mt++) {
        int row = wm * 32 + mt * 16 + (lane & 7) + 8 * ((lane >> 3) & 1);
        int jj = (lane >> 4) & 1;
        a_addr[mt] = row * 64 + ((jj ^ ((row >> 1) & 3)) << 4);
    }
#pragma unroll
    for (int p = 0; p < 4; p++) {
        int row = wn * 64 + p * 16 + (lane & 7) + 8 * ((lane >> 4) & 1);
        int jj = (lane >> 3) & 1;
        b_addr[p] = row * 64 + ((jj ^ ((row >> 1) & 3)) << 4);
    }

    float acc[2][8][4];
#pragma unroll
    for (int mt = 0; mt < 2; mt++)
#pragma unroll
        for (int nt = 0; nt < 8; nt++)
#pragma unroll
            for (int q = 0; q < 4; q++) acc[mt][nt][q] = 0.f;

    int NS = K >> 5;   // BK=32
    uint4 ra0, ra1, rb0, rb1;

    // prologue: stage 0
    ra0 = *(const uint4*)(arow + 16 * lh);
    ra1 = *(const uint4*)(arow + 16 * lh + 8);
    rb0 = *(const uint4*)(brow + 16 * lh);
    rb1 = *(const uint4*)(brow + 16 * lh + 8);
    *(uint4*)((char*)As[0] + stA0) = ra0;
    *(uint4*)((char*)As[0] + stA1) = ra1;
    *(uint4*)((char*)Bs[0] + stA0) = rb0;
    *(uint4*)((char*)Bs[0] + stA1) = rb1;
    __syncthreads();

    for (int s = 0; s < NS; s++) {
        if (s + 1 < NS) {
            int k0 = (s + 1) << 5;
            ra0 = *(const uint4*)(arow + k0 + 16 * lh);
            ra1 = *(const uint4*)(arow + k0 + 16 * lh + 8);
            rb0 = *(const uint4*)(brow + k0 + 16 * lh);
            rb1 = *(const uint4*)(brow + k0 + 16 * lh + 8);
        }
        uint32_t abase = a_sb + (s & 1) * 8192;
        uint32_t bbase = b_sb + (s & 1) * 8192;
#pragma unroll
        for (int kk = 0; kk < 2; kk++) {
            uint32_t koff = kk << 5;
            uint32_t af[2][4];
            ldmx4(af[0], abase + (a_addr[0] ^ koff));
            ldmx4(af[1], abase + (a_addr[1] ^ koff));
            uint32_t bf[4][4];   // [pair][b0_nt,b1_nt,b0_nt1,b1_nt1]
            ldmx4(bf[0], bbase + (b_addr[0] ^ koff));
            ldmx4(bf[1], bbase + (b_addr[1] ^ koff));
            ldmx4(bf[2], bbase + (b_addr[2] ^ koff));
            ldmx4(bf[3], bbase + (b_addr[3] ^ koff));
#pragma unroll
            for (int mt = 0; mt < 2; mt++)
#pragma unroll
                for (int p = 0; p < 4; p++) {
                    mma_f16(acc[mt][2 * p],     af[mt], &bf[p][0]);
                    mma_f16(acc[mt][2 * p + 1], af[mt], &bf[p][2]);
                }
        }
        if (s + 1 < NS) {
            int buf = (s + 1) & 1;
            *(uint4*)((char*)As[buf] + stA0) = ra0;
            *(uint4*)((char*)As[buf] + stA1) = ra1;
            *(uint4*)((char*)Bs[buf] + stA0) = rb0;
            *(uint4*)((char*)Bs[buf] + stA1) = rb1;
            __syncthreads();
        }
    }

    // epilogue (C fragment: rows g,g+8; cols 2c,2c+1)
    int g = lane >> 2, c = lane & 3;
#pragma unroll
    for (int mt = 0; mt < 2; mt++) {
        int row0 = bm + wm * 32 + mt * 16 + g;
        int row1 = row0 + 8;
#pragma unroll
        for (int nt = 0; nt < 8; nt++) {
            int col = bn + wn * 64 + nt * 8 + 2 * c;
            float* c0 = C + (size_t)row0 * ldc + col;
            float* c1 = C + (size_t)row1 * ldc + col;
            if (ACCUM) {
                float2 o0 = *(const float2*)c0;
                float2 o1 = *(const float2*)c1;
                float2 n0 = {acc[mt][nt][0] + o0.x, acc[mt][nt][1] + o0.y};
                float2 n1 = {acc[mt][nt][2] + o1.x, acc[mt][nt][3] + o1.y};
                *(float2*)c0 = n0;
                *(float2*)c1 = n1;
            } else {
                float bs0 = bias1[col] + bias2[col];
                float bs1 = bias1[col + 1] + bias2[col + 1];
                float2 n0 = {acc[mt][nt][0] + bs0, acc[mt][nt][1] + bs1};
                float2 n1 = {acc[mt][nt][2] + bs0, acc[mt][nt][3] + bs1};
                *(float2*)c0 = n0;
                *(float2*)c1 = n1;
            }
        }
    }
}

// ============================================================
// K3: LSTM step 0 elementwise; writes fp32 h1/c1 + half h1 for GEMM2
// ============================================================
__global__ __launch_bounds__(256) void lstm_step0(void)
{
    int e = blockIdx.x * 256 + threadIdx.x;
    int f = e >> 8, j = e & 255;
    const float* gb = g_gates + (size_t)(2 * f) * 1024;
    float ig = gb[j], gg = gb[512 + j], og = gb[768 + j];
    float c1 = sigf(ig) * tanhf(gg);
    float h1 = sigf(og) * tanhf(c1);
    g_c1[e] = c1;
    g_h1[e] = h1;
    g_h1h[e] = __float2half_rn(h1);
}

// ============================================================
// K5: LSTM step 1 + attention over {h1,h2} + output head
// ============================================================
__global__ __launch_bounds__(256) void lstm_step1_attn_out(
    const float* __restrict__ Wg_frag,
    const float* __restrict__ W_out,
    const float* __restrict__ b_out)
{
    int f = blockIdx.x;
    int j = threadIdx.x;
    const float* gb = g_gates + (size_t)(2 * f + 1) * 1024;
    float ig = gb[j], fg = gb[256 + j], gg = gb[512 + j], og = gb[768 + j];
    float c1 = g_c1[(size_t)f * 256 + j];
    float c2 = sigf(fg) * c1 + sigf(ig) * tanhf(gg);
    float h2 = sigf(og) * tanhf(c2);
    float h1 = g_h1[(size_t)f * 256 + j];

    float wg = Wg_frag[j];
    __shared__ float red[8][2];
    float p1 = warp_sum(h1 * wg);
    float p2 = warp_sum(h2 * wg);
    int w = j >> 5, lane = j & 31;
    if (lane == 0) { red[w][0] = p1; red[w][1] = p2; }
    __syncthreads();
    float l1 = 0.f, l2 = 0.f;
#pragma unroll
    for (int ww = 0; ww < 8; ww++) { l1 += red[ww][0]; l2 += red[ww][1]; }
    float m = fmaxf(l1, l2);
    float e1 = expf(l1 - m), e2 = expf(l2 - m);
    float inv = 1.0f / (e1 + e2);
    float frag = (e1 * h1 + e2 * h2) * inv;

    float4 w0 = *(const float4*)&W_out[(size_t)j * 8];
    float4 w1 = *(const float4*)&W_out[(size_t)j * 8 + 4];
    float o[8] = {frag * w0.x, frag * w0.y, frag * w0.z, frag * w0.w,
                  frag * w1.x, frag * w1.y, frag * w1.z, frag * w1.w};
#pragma unroll
    for (int t = 0; t < 8; t++) o[t] = warp_sum(o[t]);
    __shared__ float red2[8][8];
    if (lane == 0) {
#pragma unroll
        for (int t = 0; t < 8; t++) red2[w][t] = o[t];
    }
    __syncthreads();
    if (j < 8) {
        float s = 0.f;
#pragma unroll
        for (int ww = 0; ww < 8; ww++) s += red2[ww][j];
        s += b_out[j];
        g_fragout[(size_t)f * 8 + j] = fmaxf(s, 0.f);
    }
}

// ============================================================
// K6: combine scatter-sum
// ============================================================
__global__ __launch_bounds__(256) void combine_kernel(
    const int* __restrict__ src, float* __restrict__ out)
{
    int idx = blockIdx.x * 256 + threadIdx.x;
    if (idx >= N_OUTN * TOUT) return;
    int n = idx >> 3, t = idx & 7;
    float s = 0.f;
#pragma unroll
    for (int d = 0; d < 4; d++)
        s += g_fragout[(size_t)src[n * 4 + d] * 8 + t];
    out[idx] = s;
}

// ============================================================
extern "C" void kernel_launch(void* const* d_in, const int* in_sizes, int n_in,
                              void* d_out, int out_size)
{
    const float* feature = (const float*)d_in[0];
    const float* WgL     = (const float*)d_in[1];
    const float* WgR     = (const float*)d_in[2];
    const float* W_ih    = (const float*)d_in[3];
    const float* W_hh    = (const float*)d_in[4];
    const float* b_ih    = (const float*)d_in[5];
    const float* b_hh    = (const float*)d_in[6];
    const float* Wg_frag = (const float*)d_in[7];
    const float* W_out   = (const float*)d_in[8];
    const float* b_out   = (const float*)d_in[9];
    const int* lost      = (const int*)d_in[10];
    const int* ret       = (const int*)d_in[11];
    const int* join      = (const int*)d_in[12];
    const int* comb      = (const int*)d_in[13];
    float* out = (float*)d_out;

    void *p_cleav, *p_gates, *p_h1h, *p_wih, *p_whh;
    cudaGetSymbolAddress(&p_cleav, g_cleav_h);
    cudaGetSymbolAddress(&p_gates, g_gates);
    cudaGetSymbolAddress(&p_h1h, g_h1h);
    cudaGetSymbolAddress(&p_wih, g_Wih_h);
    cudaGetSymbolAddress(&p_whh, g_Whh_h);

    // K0: weight fp32 -> half
    conv_w<<<(1024 * 512 + 255) / 256, 256>>>(W_ih, W_hh);

    // K1: cleavage attention (writes half)
    cleav_kernel<<<N_CLEAV, 256>>>(feature, WgL, WgR, lost, ret);

    // GEMM1: gates[160000,1024] = cleav_h[join_src][.,512] @ Wih_h^T + (b_ih+b_hh)
    gemm_h<true, false><<<dim3(1024 / 128, (2 * N_FRAG) / 128), 256>>>(
        (const __half*)p_cleav, join, (const __half*)p_wih, b_ih, b_hh,
        (float*)p_gates, 512, 1024);

    // K3: LSTM step 0 elementwise
    lstm_step0<<<(N_FRAG * FDIM) / 256, 256>>>();

    // GEMM2: gates[odd rows] += h1_h @ Whh_h^T  (C base offset 1024, ldc 2048)
    gemm_h<false, true><<<dim3(1024 / 128, N_FRAG / 128), 256>>>(
        (const __half*)p_h1h, nullptr, (const __half*)p_whh, nullptr, nullptr,
        (float*)p_gates + 1024, 256, 2048);

    // K5: LSTM step 1 + attention + output head
    lstm_step1_attn_out<<<N_FRAG, 256>>>(Wg_frag, W_out, b_out);

    // K6: combine scatter-sum
    combine_kernel<<<(N_OUTN * TOUT + 255) / 256, 256>>>(comb, out);
}